// round 9
// baseline (speedup 1.0000x reference)
#include <cuda_runtime.h>
#include <math.h>

#define N_NODES 100000
#define N_EDGES 1600000
#define HALF_E  (N_EDGES / 2)

typedef unsigned long long u64;

__device__ float g_dot[N_EDGES];
__device__ float g_m[N_NODES];
__device__ float g_s[N_NODES];

// ---- packed f32x2 helpers ----
union PU { u64 u; float2 f; };

__device__ __forceinline__ u64 pk(float lo, float hi) {
    PU p; p.f.x = lo; p.f.y = hi; return p.u;
}
__device__ __forceinline__ float2 upk2(u64 x) { PU p; p.u = x; return p.f; }

__device__ __forceinline__ u64 fma2(u64 a, u64 b, u64 c) {
    u64 d; asm("fma.rn.f32x2 %0,%1,%2,%3;" : "=l"(d) : "l"(a), "l"(b), "l"(c)); return d;
}
__device__ __forceinline__ u64 add2(u64 a, u64 b) {
    u64 d; asm("add.rn.f32x2 %0,%1,%2;" : "=l"(d) : "l"(a), "l"(b)); return d;
}
__device__ __forceinline__ u64 mul2(u64 a, u64 b) {
    u64 d; asm("mul.rn.f32x2 %0,%1,%2;" : "=l"(d) : "l"(a), "l"(b)); return d;
}

#define C_NEG1      0xBF800000BF800000ull   // (-1.f, -1.f)
#define C_SIXTEENTH 0x3D8000003D800000ull   // (0.0625f, 0.0625f)

struct SWP {
    u64 W1[4][3][16];
    u64 b1[4][16], g1[4][16], be1[4][16];
    u64 W2[4][16][16];
    u64 b2[4][16], g2[4][16], be2[4][16];
    u64 W3a[3][16][4];   // W3_00, W3_01, W3_10
    u64 b3a[3][4];
    u64 W3_11[16][12];
    u64 b3_11[12];
    float wqs[8];        // scalar wq [2][2][2]
};

// numerically safe LN: subtract mean first, then square (matches reference)
__device__ __forceinline__ void ln_relu_pk(u64* h, const u64* g, const u64* be) {
    u64 s = h[0];
#pragma unroll
    for (int j = 1; j < 16; j++) s = add2(s, h[j]);
    u64 mu = mul2(s, C_SIXTEENTH);
    u64 vs = 0ull;
#pragma unroll
    for (int j = 0; j < 16; j++) {
        h[j] = fma2(mu, C_NEG1, h[j]);      // h <- h - mu
        vs = fma2(h[j], h[j], vs);
    }
    float2 V = upk2(vs);
    u64 inv = pk(rsqrtf(fmaf(V.x, 0.0625f, 1e-5f)),
                 rsqrtf(fmaf(V.y, 0.0625f, 1e-5f)));
#pragma unroll
    for (int j = 0; j < 16; j++) {
        u64 tj = mul2(h[j], inv);
        PU val; val.u = fma2(tj, g[j], be[j]);
        val.f.x = fmaxf(val.f.x, 0.f);
        val.f.y = fmaxf(val.f.y, 0.f);
        h[j] = val.u;
    }
}

// loop orders chosen so weight reads are consecutive u64 -> LDS.128 merges
template <int OUT>
__device__ __forceinline__ void radial_pk(const SWP& sw, int i, const u64* W3, const u64* b3,
                                          u64 va, u64 vb, u64 vc, u64* R) {
    u64 h[16];
#pragma unroll
    for (int j = 0; j < 16; j++) h[j] = sw.b1[i][j];
#pragma unroll
    for (int j = 0; j < 16; j++) h[j] = fma2(va, sw.W1[i][0][j], h[j]);
#pragma unroll
    for (int j = 0; j < 16; j++) h[j] = fma2(vb, sw.W1[i][1][j], h[j]);
#pragma unroll
    for (int j = 0; j < 16; j++) h[j] = fma2(vc, sw.W1[i][2][j], h[j]);
    ln_relu_pk(h, sw.g1[i], sw.be1[i]);

    u64 acc[16];
#pragma unroll
    for (int j = 0; j < 16; j++) acc[j] = sw.b2[i][j];
#pragma unroll
    for (int k = 0; k < 16; k++) {
#pragma unroll
        for (int j = 0; j < 16; j++)
            acc[j] = fma2(h[k], sw.W2[i][k][j], acc[j]);   // consecutive j
    }
    ln_relu_pk(acc, sw.g2[i], sw.be2[i]);

#pragma unroll
    for (int o = 0; o < OUT; o++) R[o] = b3[o];
#pragma unroll
    for (int k = 0; k < 16; k++) {
#pragma unroll
        for (int o = 0; o < OUT; o++)
            R[o] = fma2(acc[k], W3[k * OUT + o], R[o]);    // consecutive o
    }
}

__device__ __forceinline__ void atomicMaxF(float* addr, float val) {
    if (val >= 0.f) atomicMax((int*)addr, __float_as_int(val));
    else            atomicMin((unsigned int*)addr, __float_as_uint(val));
}

__global__ void init_kernel() {
    int n = blockIdx.x * blockDim.x + threadIdx.x;
    if (n < N_NODES) {
        g_m[n] = -INFINITY;
        g_s[n] = 0.f;
    }
}

__global__ __launch_bounds__(128, 3) void edge_kernel(
    const float* __restrict__ f0, const float* __restrict__ f1,
    const float* __restrict__ dist,
    const int* __restrict__ u, const int* __restrict__ v,
    const float* __restrict__ wq,
    const float* __restrict__ wj00, const float* __restrict__ wj01,
    const float* __restrict__ wj10, const float* __restrict__ wj11,
    const float* __restrict__ rW1, const float* __restrict__ rb1,
    const float* __restrict__ g1, const float* __restrict__ be1,
    const float* __restrict__ rW2, const float* __restrict__ rb2,
    const float* __restrict__ g2, const float* __restrict__ be2,
    const float* __restrict__ W3_00, const float* __restrict__ b3_00,
    const float* __restrict__ W3_01, const float* __restrict__ b3_01,
    const float* __restrict__ W3_10, const float* __restrict__ b3_10,
    const float* __restrict__ W3_11, const float* __restrict__ b3_11)
{
    __shared__ SWP sw;
    {
        int t = threadIdx.x;
#define CPYP(dst, src, n) for (int i = t; i < (n); i += 128) ((u64*)(dst))[i] = pk((src)[i], (src)[i])
        CPYP(sw.W1, rW1, 192);
        CPYP(sw.b1, rb1, 64);
        CPYP(sw.g1, g1, 64);
        CPYP(sw.be1, be1, 64);
        CPYP(sw.W2, rW2, 1024);
        CPYP(sw.b2, rb2, 64);
        CPYP(sw.g2, g2, 64);
        CPYP(sw.be2, be2, 64);
        CPYP(sw.W3a[0], W3_00, 64);
        CPYP(sw.W3a[1], W3_01, 64);
        CPYP(sw.W3a[2], W3_10, 64);
        CPYP(sw.b3a[0], b3_00, 4);
        CPYP(sw.b3a[1], b3_01, 4);
        CPYP(sw.b3a[2], b3_10, 4);
        CPYP(sw.W3_11, W3_11, 192);
        CPYP(sw.b3_11, b3_11, 12);
#undef CPYP
        for (int i = t; i < 8; i += 128) sw.wqs[i] = wq[i];
    }
    __syncthreads();

    int t = blockIdx.x * 128 + threadIdx.x;   // grid exactly HALF_E/128; edges 2t, 2t+1

    int2 uu = ((const int2*)u)[t];
    int2 vv = ((const int2*)v)[t];
    float2 dd = ((const float2*)dist)[t];

    float2 fu_a = ((const float2*)f0)[uu.x];
    float2 fu_b = ((const float2*)f0)[uu.y];
    float2 fv_a = ((const float2*)f0)[vv.x];
    float2 fv_b = ((const float2*)f0)[vv.y];

    float f1a[6], f1b[6];
    {
        const float2* p0 = (const float2*)f1 + 3 * vv.x;
        const float2* p1 = (const float2*)f1 + 3 * vv.y;
        float2 x;
        x = p0[0]; f1a[0] = x.x; f1a[1] = x.y;
        x = p0[1]; f1a[2] = x.x; f1a[3] = x.y;
        x = p0[2]; f1a[4] = x.x; f1a[5] = x.y;
        x = p1[0]; f1b[0] = x.x; f1b[1] = x.y;
        x = p1[1]; f1b[2] = x.x; f1b[3] = x.y;
        x = p1[2]; f1b[4] = x.x; f1b[5] = x.y;
    }

    u64 va = pk(fu_a.x * fv_a.x, fu_b.x * fv_b.x);
    u64 vb = pk(fu_a.y * fv_a.y, fu_b.y * fv_b.y);
    u64 vc = pk(dd.x, dd.y);

    u64 Rp[12];
    float k00[2], k01[2];        // l=0 accumulators, per edge, per o
    float k1[2][2][3];           // [edge][o][l]

    // ---- i=0 (l=0,k=0) ----
    radial_pk<4>(sw, 0, (const u64*)sw.W3a[0], sw.b3a[0], va, vb, vc, Rp);
    {
        float2 w00 = ((const float2*)wj00)[t];
        float2 r0 = upk2(Rp[0]), r1 = upk2(Rp[1]), r2 = upk2(Rp[2]), r3 = upk2(Rp[3]);
        k00[0] = w00.x * fmaf(r0.x, fv_a.x, r1.x * fv_a.y);
        k01[0] = w00.x * fmaf(r2.x, fv_a.x, r3.x * fv_a.y);
        k00[1] = w00.y * fmaf(r0.y, fv_b.x, r1.y * fv_b.y);
        k01[1] = w00.y * fmaf(r2.y, fv_b.x, r3.y * fv_b.y);
    }

    // ---- i=1 (l=0,k=1) ----
    radial_pk<4>(sw, 1, (const u64*)sw.W3a[1], sw.b3a[1], va, vb, vc, Rp);
    {
        const float2* wp = (const float2*)wj01;
        float2 a = wp[3 * t], b = wp[3 * t + 1], c = wp[3 * t + 2];
        float2 r0 = upk2(Rp[0]), r1 = upk2(Rp[1]), r2 = upk2(Rp[2]), r3 = upk2(Rp[3]);
        {   // edge 0: w = {a.x, a.y, b.x}
            float t0 = fmaf(a.x, f1a[0], fmaf(a.y, f1a[1], b.x * f1a[2]));
            float t1 = fmaf(a.x, f1a[3], fmaf(a.y, f1a[4], b.x * f1a[5]));
            k00[0] = fmaf(r0.x, t0, fmaf(r1.x, t1, k00[0]));
            k01[0] = fmaf(r2.x, t0, fmaf(r3.x, t1, k01[0]));
        }
        {   // edge 1: w = {b.y, c.x, c.y}
            float t0 = fmaf(b.y, f1b[0], fmaf(c.x, f1b[1], c.y * f1b[2]));
            float t1 = fmaf(b.y, f1b[3], fmaf(c.x, f1b[4], c.y * f1b[5]));
            k00[1] = fmaf(r0.y, t0, fmaf(r1.y, t1, k00[1]));
            k01[1] = fmaf(r2.y, t0, fmaf(r3.y, t1, k01[1]));
        }
    }

    // ---- i=2 (l=1,k=0) ----
    radial_pk<4>(sw, 2, (const u64*)sw.W3a[2], sw.b3a[2], va, vb, vc, Rp);
    {
        const float2* wp = (const float2*)wj10;
        float2 a = wp[3 * t], b = wp[3 * t + 1], c = wp[3 * t + 2];
        float2 r0 = upk2(Rp[0]), r1 = upk2(Rp[1]), r2 = upk2(Rp[2]), r3 = upk2(Rp[3]);
        float d0 = fmaf(r0.x, fv_a.x, r1.x * fv_a.y);
        float d1 = fmaf(r2.x, fv_a.x, r3.x * fv_a.y);
        float e0w[3] = {a.x, a.y, b.x};
        float e1w[3] = {b.y, c.x, c.y};
#pragma unroll
        for (int l = 0; l < 3; l++) { k1[0][0][l] = d0 * e0w[l]; k1[0][1][l] = d1 * e0w[l]; }
        float d0b = fmaf(r0.y, fv_b.x, r1.y * fv_b.y);
        float d1b = fmaf(r2.y, fv_b.x, r3.y * fv_b.y);
#pragma unroll
        for (int l = 0; l < 3; l++) { k1[1][0][l] = d0b * e1w[l]; k1[1][1][l] = d1b * e1w[l]; }
    }

    // ---- i=3 (l=1,k=1) ----
    radial_pk<12>(sw, 3, (const u64*)sw.W3_11, sw.b3_11, va, vb, vc, Rp);
    {
        const float2* wp = (const float2*)wj11;
#pragma unroll
        for (int p = 0; p < 2; p++) {
            float w27[27];
            if (p == 0) {
#pragma unroll
                for (int k = 0; k < 13; k++) {
                    float2 x = wp[27 * t + k];
                    w27[2 * k] = x.x; w27[2 * k + 1] = x.y;
                }
                w27[26] = wj11[54 * t + 26];
            } else {
                w27[0] = wj11[54 * t + 27];
#pragma unroll
                for (int k = 0; k < 13; k++) {
                    float2 x = wp[27 * t + 14 + k];
                    w27[2 * k + 1] = x.x; w27[2 * k + 2] = x.y;
                }
            }
            const float* f1p = (p == 0) ? f1a : f1b;
#pragma unroll
            for (int j = 0; j < 3; j++) {
                float2 R0 = upk2(Rp[4 * j + 0]), R1 = upk2(Rp[4 * j + 1]);
                float2 R2 = upk2(Rp[4 * j + 2]), R3 = upk2(Rp[4 * j + 3]);
                float r0 = (p == 0) ? R0.x : R0.y;
                float r1 = (p == 0) ? R1.x : R1.y;
                float r2 = (p == 0) ? R2.x : R2.y;
                float r3 = (p == 0) ? R3.x : R3.y;
#pragma unroll
                for (int l = 0; l < 3; l++) {
                    float s0 = fmaf(w27[9 * j + 3 * l], f1p[0],
                               fmaf(w27[9 * j + 3 * l + 1], f1p[1], w27[9 * j + 3 * l + 2] * f1p[2]));
                    float s1 = fmaf(w27[9 * j + 3 * l], f1p[3],
                               fmaf(w27[9 * j + 3 * l + 1], f1p[4], w27[9 * j + 3 * l + 2] * f1p[5]));
                    k1[p][0][l] = fmaf(r0, s0, fmaf(r1, s1, k1[p][0][l]));
                    k1[p][1][l] = fmaf(r2, s0, fmaf(r3, s1, k1[p][1][l]));
                }
            }
        }
    }

    // ---- q·k dot, store, atomicMax ----
    float dots[2];
#pragma unroll
    for (int p = 0; p < 2; p++) {
        float2 fv = (p == 0) ? fv_a : fv_b;
        const float* f1p = (p == 0) ? f1a : f1b;
        float dot = 0.f;
#pragma unroll
        for (int o = 0; o < 2; o++) {
            float q0 = fmaf(sw.wqs[o * 2 + 0], fv.x, sw.wqs[o * 2 + 1] * fv.y);
            dot = fmaf(q0, (o == 0 ? k00[p] : k01[p]), dot);
#pragma unroll
            for (int m = 0; m < 3; m++) {
                float q1 = fmaf(sw.wqs[4 + o * 2 + 0], f1p[m], sw.wqs[4 + o * 2 + 1] * f1p[3 + m]);
                dot = fmaf(q1, k1[p][o][m], dot);
            }
        }
        dots[p] = dot;
    }

    float2 dw; dw.x = dots[0]; dw.y = dots[1];
    ((float2*)g_dot)[t] = dw;
    atomicMaxF(&g_m[vv.x], dots[0]);
    atomicMaxF(&g_m[vv.y], dots[1]);
}

__global__ void exp_kernel(const int* __restrict__ v, float* __restrict__ out) {
    int e = blockIdx.x * 256 + threadIdx.x;
    if (e >= N_EDGES) return;
    int vv = v[e];
    float p = __expf(g_dot[e] - g_m[vv]);
    out[e] = p;
    atomicAdd(&g_s[vv], p);
}

__global__ void norm_kernel(const int* __restrict__ v, float* __restrict__ out) {
    int t = blockIdx.x * 256 + threadIdx.x;
    if (t >= HALF_E) return;
    int2 vv = ((const int2*)v)[t];
    float2 o = ((const float2*)out)[t];
    o.x = o.x / g_s[vv.x];
    o.y = o.y / g_s[vv.y];
    ((float2*)out)[t] = o;
}

extern "C" void kernel_launch(void* const* d_in, const int* in_sizes, int n_in,
                              void* d_out, int out_size) {
    const float* f0    = (const float*)d_in[0];
    const float* f1    = (const float*)d_in[1];
    const float* dist  = (const float*)d_in[2];
    const int*   u     = (const int*)d_in[3];
    const int*   v     = (const int*)d_in[4];
    const float* wq    = (const float*)d_in[5];
    const float* wj00  = (const float*)d_in[6];
    const float* wj01  = (const float*)d_in[7];
    const float* wj10  = (const float*)d_in[8];
    const float* wj11  = (const float*)d_in[9];
    const float* rW1   = (const float*)d_in[10];
    const float* rb1   = (const float*)d_in[11];
    const float* g1    = (const float*)d_in[12];
    const float* be1   = (const float*)d_in[13];
    const float* rW2   = (const float*)d_in[14];
    const float* rb2   = (const float*)d_in[15];
    const float* g2    = (const float*)d_in[16];
    const float* be2   = (const float*)d_in[17];
    const float* W3_00 = (const float*)d_in[18];
    const float* b3_00 = (const float*)d_in[19];
    const float* W3_01 = (const float*)d_in[20];
    const float* b3_01 = (const float*)d_in[21];
    const float* W3_10 = (const float*)d_in[22];
    const float* b3_10 = (const float*)d_in[23];
    const float* W3_11 = (const float*)d_in[24];
    const float* b3_11 = (const float*)d_in[25];
    float* out = (float*)d_out;

    init_kernel<<<(N_NODES + 255) / 256, 256>>>();
    edge_kernel<<<HALF_E / 128, 128>>>(
        f0, f1, dist, u, v, wq, wj00, wj01, wj10, wj11,
        rW1, rb1, g1, be1, rW2, rb2, g2, be2,
        W3_00, b3_00, W3_01, b3_01, W3_10, b3_10, W3_11, b3_11);
    exp_kernel<<<(N_EDGES + 255) / 256, 256>>>(v, out);
    norm_kernel<<<HALF_E / 256, 256>>>(v, out);
}

// round 10
// speedup vs baseline: 1.0383x; 1.0383x over previous
#include <cuda_runtime.h>
#include <math.h>

#define N_NODES 100000
#define N_EDGES 1600000
#define HALF_E  (N_EDGES / 2)
#define WJPITCH 29

typedef unsigned long long u64;

__device__ float g_dot[N_EDGES];
__device__ float g_m[N_NODES];
__device__ float g_s[N_NODES];

// ---- packed f32x2 helpers ----
union PU { u64 u; float2 f; };

__device__ __forceinline__ u64 pk(float lo, float hi) {
    PU p; p.f.x = lo; p.f.y = hi; return p.u;
}
__device__ __forceinline__ float2 upk2(u64 x) { PU p; p.u = x; return p.f; }

__device__ __forceinline__ u64 fma2(u64 a, u64 b, u64 c) {
    u64 d; asm("fma.rn.f32x2 %0,%1,%2,%3;" : "=l"(d) : "l"(a), "l"(b), "l"(c)); return d;
}
__device__ __forceinline__ u64 add2(u64 a, u64 b) {
    u64 d; asm("add.rn.f32x2 %0,%1,%2;" : "=l"(d) : "l"(a), "l"(b)); return d;
}
__device__ __forceinline__ u64 mul2(u64 a, u64 b) {
    u64 d; asm("mul.rn.f32x2 %0,%1,%2;" : "=l"(d) : "l"(a), "l"(b)); return d;
}

#define C_NEG1      0xBF800000BF800000ull   // (-1.f, -1.f)
#define C_SIXTEENTH 0x3D8000003D800000ull   // (0.0625f, 0.0625f)

struct SWP {
    u64 W1[4][3][16];
    u64 b1[4][16], g1[4][16], be1[4][16];
    u64 W2[4][16][16];
    u64 b2[4][16], g2[4][16], be2[4][16];
    u64 W3a[3][16][4];   // W3_00, W3_01, W3_10
    u64 b3a[3][4];
    u64 W3_11[16][12];
    u64 b3_11[12];
    float wqs[8];        // scalar wq [2][2][2]
};

// numerically safe LN: subtract mean first, then square (matches reference)
__device__ __forceinline__ void ln_relu_pk(u64* h, const u64* g, const u64* be) {
    u64 s = h[0];
#pragma unroll
    for (int j = 1; j < 16; j++) s = add2(s, h[j]);
    u64 mu = mul2(s, C_SIXTEENTH);
    u64 vs = 0ull;
#pragma unroll
    for (int j = 0; j < 16; j++) {
        h[j] = fma2(mu, C_NEG1, h[j]);      // h <- h - mu
        vs = fma2(h[j], h[j], vs);
    }
    float2 V = upk2(vs);
    u64 inv = pk(rsqrtf(fmaf(V.x, 0.0625f, 1e-5f)),
                 rsqrtf(fmaf(V.y, 0.0625f, 1e-5f)));
#pragma unroll
    for (int j = 0; j < 16; j++) {
        u64 tj = mul2(h[j], inv);
        PU val; val.u = fma2(tj, g[j], be[j]);
        val.f.x = fmaxf(val.f.x, 0.f);
        val.f.y = fmaxf(val.f.y, 0.f);
        h[j] = val.u;
    }
}

template <int OUT>
__device__ __forceinline__ void radial_pk(const SWP& sw, int i, const u64* W3, const u64* b3,
                                          u64 va, u64 vb, u64 vc, u64* R) {
    u64 h[16];
#pragma unroll
    for (int j = 0; j < 16; j++) h[j] = sw.b1[i][j];
#pragma unroll
    for (int j = 0; j < 16; j++) h[j] = fma2(va, sw.W1[i][0][j], h[j]);
#pragma unroll
    for (int j = 0; j < 16; j++) h[j] = fma2(vb, sw.W1[i][1][j], h[j]);
#pragma unroll
    for (int j = 0; j < 16; j++) h[j] = fma2(vc, sw.W1[i][2][j], h[j]);
    ln_relu_pk(h, sw.g1[i], sw.be1[i]);

    u64 acc[16];
#pragma unroll
    for (int j = 0; j < 16; j++) acc[j] = sw.b2[i][j];
#pragma unroll
    for (int k = 0; k < 16; k++) {
#pragma unroll
        for (int j = 0; j < 16; j++)
            acc[j] = fma2(h[k], sw.W2[i][k][j], acc[j]);
    }
    ln_relu_pk(acc, sw.g2[i], sw.be2[i]);

#pragma unroll
    for (int o = 0; o < OUT; o++) R[o] = b3[o];
#pragma unroll
    for (int k = 0; k < 16; k++) {
#pragma unroll
        for (int o = 0; o < OUT; o++)
            R[o] = fma2(acc[k], W3[k * OUT + o], R[o]);
    }
}

__device__ __forceinline__ void atomicMaxF(float* addr, float val) {
    if (val >= 0.f) atomicMax((int*)addr, __float_as_int(val));
    else            atomicMin((unsigned int*)addr, __float_as_uint(val));
}

__global__ void init_kernel() {
    int n = blockIdx.x * blockDim.x + threadIdx.x;
    if (n < N_NODES) {
        g_m[n] = -INFINITY;
        g_s[n] = 0.f;
    }
}

__global__ __launch_bounds__(128, 3) void edge_kernel(
    const float* __restrict__ f0, const float* __restrict__ f1,
    const float* __restrict__ dist,
    const int* __restrict__ u, const int* __restrict__ v,
    const float* __restrict__ wq,
    const float* __restrict__ wj00, const float* __restrict__ wj01,
    const float* __restrict__ wj10, const float* __restrict__ wj11,
    const float* __restrict__ rW1, const float* __restrict__ rb1,
    const float* __restrict__ g1, const float* __restrict__ be1,
    const float* __restrict__ rW2, const float* __restrict__ rb2,
    const float* __restrict__ g2, const float* __restrict__ be2,
    const float* __restrict__ W3_00, const float* __restrict__ b3_00,
    const float* __restrict__ W3_01, const float* __restrict__ b3_01,
    const float* __restrict__ W3_10, const float* __restrict__ b3_10,
    const float* __restrict__ W3_11, const float* __restrict__ b3_11)
{
    __shared__ SWP sw;
    __shared__ float wj11s[256 * WJPITCH];   // 256 edges/block, pitch 29 (2-way max LDS conflicts)
    {
        int t = threadIdx.x;
#define CPYP(dst, src, n) for (int i = t; i < (n); i += 128) ((u64*)(dst))[i] = pk((src)[i], (src)[i])
        CPYP(sw.W1, rW1, 192);
        CPYP(sw.b1, rb1, 64);
        CPYP(sw.g1, g1, 64);
        CPYP(sw.be1, be1, 64);
        CPYP(sw.W2, rW2, 1024);
        CPYP(sw.b2, rb2, 64);
        CPYP(sw.g2, g2, 64);
        CPYP(sw.be2, be2, 64);
        CPYP(sw.W3a[0], W3_00, 64);
        CPYP(sw.W3a[1], W3_01, 64);
        CPYP(sw.W3a[2], W3_10, 64);
        CPYP(sw.b3a[0], b3_00, 4);
        CPYP(sw.b3a[1], b3_01, 4);
        CPYP(sw.b3a[2], b3_10, 4);
        CPYP(sw.W3_11, W3_11, 192);
        CPYP(sw.b3_11, b3_11, 12);
#undef CPYP
        for (int i = t; i < 8; i += 128) sw.wqs[i] = wq[i];

        // coalesced staging of this block's wj11 slab: edges [256b, 256b+256)
        const float* src = wj11 + (long long)blockIdx.x * 256 * 27;
#pragma unroll
        for (int k = 0; k < 54; k++) {
            int i = t + 128 * k;            // 0 .. 6911
            int e = i / 27, j = i - e * 27;
            wj11s[e * WJPITCH + j] = src[i];
        }
    }
    __syncthreads();

    int t = blockIdx.x * 128 + threadIdx.x;   // pair index; edges 2t, 2t+1

    int2 uu = ((const int2*)u)[t];
    int2 vv = ((const int2*)v)[t];
    float2 dd = ((const float2*)dist)[t];

    float2 fu_a = ((const float2*)f0)[uu.x];
    float2 fu_b = ((const float2*)f0)[uu.y];
    float2 fv_a = ((const float2*)f0)[vv.x];
    float2 fv_b = ((const float2*)f0)[vv.y];

    float f1a[6], f1b[6];
    {
        const float2* p0 = (const float2*)f1 + 3 * vv.x;
        const float2* p1 = (const float2*)f1 + 3 * vv.y;
        float2 x;
        x = p0[0]; f1a[0] = x.x; f1a[1] = x.y;
        x = p0[1]; f1a[2] = x.x; f1a[3] = x.y;
        x = p0[2]; f1a[4] = x.x; f1a[5] = x.y;
        x = p1[0]; f1b[0] = x.x; f1b[1] = x.y;
        x = p1[1]; f1b[2] = x.x; f1b[3] = x.y;
        x = p1[2]; f1b[4] = x.x; f1b[5] = x.y;
    }

    u64 va = pk(fu_a.x * fv_a.x, fu_b.x * fv_b.x);
    u64 vb = pk(fu_a.y * fv_a.y, fu_b.y * fv_b.y);
    u64 vc = pk(dd.x, dd.y);

    u64 Rp[12];
    float k00[2], k01[2];
    float k1[2][2][3];

    // ---- i=0 (l=0,k=0) ----
    radial_pk<4>(sw, 0, (const u64*)sw.W3a[0], sw.b3a[0], va, vb, vc, Rp);
    {
        float2 w00 = ((const float2*)wj00)[t];
        float2 r0 = upk2(Rp[0]), r1 = upk2(Rp[1]), r2 = upk2(Rp[2]), r3 = upk2(Rp[3]);
        k00[0] = w00.x * fmaf(r0.x, fv_a.x, r1.x * fv_a.y);
        k01[0] = w00.x * fmaf(r2.x, fv_a.x, r3.x * fv_a.y);
        k00[1] = w00.y * fmaf(r0.y, fv_b.x, r1.y * fv_b.y);
        k01[1] = w00.y * fmaf(r2.y, fv_b.x, r3.y * fv_b.y);
    }

    // ---- i=1 (l=0,k=1) ----
    radial_pk<4>(sw, 1, (const u64*)sw.W3a[1], sw.b3a[1], va, vb, vc, Rp);
    {
        const float2* wp = (const float2*)wj01;
        float2 a = wp[3 * t], b = wp[3 * t + 1], c = wp[3 * t + 2];
        float2 r0 = upk2(Rp[0]), r1 = upk2(Rp[1]), r2 = upk2(Rp[2]), r3 = upk2(Rp[3]);
        {   // edge 0: w = {a.x, a.y, b.x}
            float t0 = fmaf(a.x, f1a[0], fmaf(a.y, f1a[1], b.x * f1a[2]));
            float t1 = fmaf(a.x, f1a[3], fmaf(a.y, f1a[4], b.x * f1a[5]));
            k00[0] = fmaf(r0.x, t0, fmaf(r1.x, t1, k00[0]));
            k01[0] = fmaf(r2.x, t0, fmaf(r3.x, t1, k01[0]));
        }
        {   // edge 1: w = {b.y, c.x, c.y}
            float t0 = fmaf(b.y, f1b[0], fmaf(c.x, f1b[1], c.y * f1b[2]));
            float t1 = fmaf(b.y, f1b[3], fmaf(c.x, f1b[4], c.y * f1b[5]));
            k00[1] = fmaf(r0.y, t0, fmaf(r1.y, t1, k00[1]));
            k01[1] = fmaf(r2.y, t0, fmaf(r3.y, t1, k01[1]));
        }
    }

    // ---- i=2 (l=1,k=0) ----
    radial_pk<4>(sw, 2, (const u64*)sw.W3a[2], sw.b3a[2], va, vb, vc, Rp);
    {
        const float2* wp = (const float2*)wj10;
        float2 a = wp[3 * t], b = wp[3 * t + 1], c = wp[3 * t + 2];
        float2 r0 = upk2(Rp[0]), r1 = upk2(Rp[1]), r2 = upk2(Rp[2]), r3 = upk2(Rp[3]);
        float d0 = fmaf(r0.x, fv_a.x, r1.x * fv_a.y);
        float d1 = fmaf(r2.x, fv_a.x, r3.x * fv_a.y);
        float e0w[3] = {a.x, a.y, b.x};
        float e1w[3] = {b.y, c.x, c.y};
#pragma unroll
        for (int l = 0; l < 3; l++) { k1[0][0][l] = d0 * e0w[l]; k1[0][1][l] = d1 * e0w[l]; }
        float d0b = fmaf(r0.y, fv_b.x, r1.y * fv_b.y);
        float d1b = fmaf(r2.y, fv_b.x, r3.y * fv_b.y);
#pragma unroll
        for (int l = 0; l < 3; l++) { k1[1][0][l] = d0b * e1w[l]; k1[1][1][l] = d1b * e1w[l]; }
    }

    // ---- i=3 (l=1,k=1): wj11 from shared staging ----
    radial_pk<12>(sw, 3, (const u64*)sw.W3_11, sw.b3_11, va, vb, vc, Rp);
    {
#pragma unroll
        for (int p = 0; p < 2; p++) {
            const float* wr = &wj11s[(2 * threadIdx.x + p) * WJPITCH];
            const float* f1p = (p == 0) ? f1a : f1b;
#pragma unroll
            for (int j = 0; j < 3; j++) {
                float2 R0 = upk2(Rp[4 * j + 0]), R1 = upk2(Rp[4 * j + 1]);
                float2 R2 = upk2(Rp[4 * j + 2]), R3 = upk2(Rp[4 * j + 3]);
                float r0 = (p == 0) ? R0.x : R0.y;
                float r1 = (p == 0) ? R1.x : R1.y;
                float r2 = (p == 0) ? R2.x : R2.y;
                float r3 = (p == 0) ? R3.x : R3.y;
#pragma unroll
                for (int l = 0; l < 3; l++) {
                    float w0 = wr[9 * j + 3 * l], w1 = wr[9 * j + 3 * l + 1], w2 = wr[9 * j + 3 * l + 2];
                    float s0 = fmaf(w0, f1p[0], fmaf(w1, f1p[1], w2 * f1p[2]));
                    float s1 = fmaf(w0, f1p[3], fmaf(w1, f1p[4], w2 * f1p[5]));
                    k1[p][0][l] = fmaf(r0, s0, fmaf(r1, s1, k1[p][0][l]));
                    k1[p][1][l] = fmaf(r2, s0, fmaf(r3, s1, k1[p][1][l]));
                }
            }
        }
    }

    // ---- q·k dot, store, atomicMax ----
    float dots[2];
#pragma unroll
    for (int p = 0; p < 2; p++) {
        float2 fv = (p == 0) ? fv_a : fv_b;
        const float* f1p = (p == 0) ? f1a : f1b;
        float dot = 0.f;
#pragma unroll
        for (int o = 0; o < 2; o++) {
            float q0 = fmaf(sw.wqs[o * 2 + 0], fv.x, sw.wqs[o * 2 + 1] * fv.y);
            dot = fmaf(q0, (o == 0 ? k00[p] : k01[p]), dot);
#pragma unroll
            for (int m = 0; m < 3; m++) {
                float q1 = fmaf(sw.wqs[4 + o * 2 + 0], f1p[m], sw.wqs[4 + o * 2 + 1] * f1p[3 + m]);
                dot = fmaf(q1, k1[p][o][m], dot);
            }
        }
        dots[p] = dot;
    }

    float2 dw; dw.x = dots[0]; dw.y = dots[1];
    ((float2*)g_dot)[t] = dw;
    atomicMaxF(&g_m[vv.x], dots[0]);
    atomicMaxF(&g_m[vv.y], dots[1]);
}

__global__ void exp_kernel(const int* __restrict__ v, float* __restrict__ out) {
    int e = blockIdx.x * 256 + threadIdx.x;
    if (e >= N_EDGES) return;
    int vv = v[e];
    float p = __expf(g_dot[e] - g_m[vv]);
    out[e] = p;
    atomicAdd(&g_s[vv], p);
}

__global__ void norm_kernel(const int* __restrict__ v, float* __restrict__ out) {
    int t = blockIdx.x * 256 + threadIdx.x;
    if (t >= HALF_E) return;
    int2 vv = ((const int2*)v)[t];
    float2 o = ((const float2*)out)[t];
    o.x = o.x / g_s[vv.x];
    o.y = o.y / g_s[vv.y];
    ((float2*)out)[t] = o;
}

extern "C" void kernel_launch(void* const* d_in, const int* in_sizes, int n_in,
                              void* d_out, int out_size) {
    const float* f0    = (const float*)d_in[0];
    const float* f1    = (const float*)d_in[1];
    const float* dist  = (const float*)d_in[2];
    const int*   u     = (const int*)d_in[3];
    const int*   v     = (const int*)d_in[4];
    const float* wq    = (const float*)d_in[5];
    const float* wj00  = (const float*)d_in[6];
    const float* wj01  = (const float*)d_in[7];
    const float* wj10  = (const float*)d_in[8];
    const float* wj11  = (const float*)d_in[9];
    const float* rW1   = (const float*)d_in[10];
    const float* rb1   = (const float*)d_in[11];
    const float* g1    = (const float*)d_in[12];
    const float* be1   = (const float*)d_in[13];
    const float* rW2   = (const float*)d_in[14];
    const float* rb2   = (const float*)d_in[15];
    const float* g2    = (const float*)d_in[16];
    const float* be2   = (const float*)d_in[17];
    const float* W3_00 = (const float*)d_in[18];
    const float* b3_00 = (const float*)d_in[19];
    const float* W3_01 = (const float*)d_in[20];
    const float* b3_01 = (const float*)d_in[21];
    const float* W3_10 = (const float*)d_in[22];
    const float* b3_10 = (const float*)d_in[23];
    const float* W3_11 = (const float*)d_in[24];
    const float* b3_11 = (const float*)d_in[25];
    float* out = (float*)d_out;

    init_kernel<<<(N_NODES + 255) / 256, 256>>>();
    edge_kernel<<<HALF_E / 128, 128>>>(
        f0, f1, dist, u, v, wq, wj00, wj01, wj10, wj11,
        rW1, rb1, g1, be1, rW2, rb2, g2, be2,
        W3_00, b3_00, W3_01, b3_01, W3_10, b3_10, W3_11, b3_11);
    exp_kernel<<<(N_EDGES + 255) / 256, 256>>>(v, out);
    norm_kernel<<<HALF_E / 256, 256>>>(v, out);
}

// round 11
// speedup vs baseline: 1.0395x; 1.0011x over previous
#include <cuda_runtime.h>
#include <math.h>

#define N_NODES 100000
#define N_EDGES 1600000
#define HALF_E  (N_EDGES / 2)
#define WJPITCH 29

typedef unsigned long long u64;

__device__ float g_dot[N_EDGES];
__device__ float g_m[N_NODES];
__device__ float g_s[N_NODES];

// ---- packed f32x2 helpers ----
union PU { u64 u; float2 f; };

__device__ __forceinline__ u64 pk(float lo, float hi) {
    PU p; p.f.x = lo; p.f.y = hi; return p.u;
}
__device__ __forceinline__ float2 upk2(u64 x) { PU p; p.u = x; return p.f; }

__device__ __forceinline__ u64 fma2(u64 a, u64 b, u64 c) {
    u64 d; asm("fma.rn.f32x2 %0,%1,%2,%3;" : "=l"(d) : "l"(a), "l"(b), "l"(c)); return d;
}
__device__ __forceinline__ u64 add2(u64 a, u64 b) {
    u64 d; asm("add.rn.f32x2 %0,%1,%2;" : "=l"(d) : "l"(a), "l"(b)); return d;
}
__device__ __forceinline__ u64 mul2(u64 a, u64 b) {
    u64 d; asm("mul.rn.f32x2 %0,%1,%2;" : "=l"(d) : "l"(a), "l"(b)); return d;
}

#define C_NEG1      0xBF800000BF800000ull   // (-1.f, -1.f)
#define C_SIXTEENTH 0x3D8000003D800000ull   // (0.0625f, 0.0625f)

// weights packed across MLP PAIRS: lane lo = MLP 2p, lane hi = MLP 2p+1
struct SWQ {
    u64 W1[2][3][16];
    u64 b1[2][16], g1[2][16], be1[2][16];
    u64 W2[2][16][16];
    u64 b2[2][16], g2[2][16], be2[2][16];
    u64 W3p0[16][4];    // (W3_00, W3_01)
    u64 b3p0[4];
    u64 W3p1[16][12];   // o<4: (W3_10, W3_11); o>=4: (0, W3_11)
    u64 b3p1[12];
    float wqs[8];
};

// packed LN (each lane an independent LN): subtract-mean-then-square (safe)
__device__ __forceinline__ void ln_relu_pk(u64* h, const u64* g, const u64* be) {
    u64 s = h[0];
#pragma unroll
    for (int j = 1; j < 16; j++) s = add2(s, h[j]);
    u64 mu = mul2(s, C_SIXTEENTH);
    u64 vs = 0ull;
#pragma unroll
    for (int j = 0; j < 16; j++) {
        h[j] = fma2(mu, C_NEG1, h[j]);
        vs = fma2(h[j], h[j], vs);
    }
    float2 V = upk2(vs);
    u64 inv = pk(rsqrtf(fmaf(V.x, 0.0625f, 1e-5f)),
                 rsqrtf(fmaf(V.y, 0.0625f, 1e-5f)));
#pragma unroll
    for (int j = 0; j < 16; j++) {
        u64 tj = mul2(h[j], inv);
        PU val; val.u = fma2(tj, g[j], be[j]);
        val.f.x = fmaxf(val.f.x, 0.f);
        val.f.y = fmaxf(val.f.y, 0.f);
        h[j] = val.u;
    }
}

// one packed radial covering MLP pair p; input identical in both lanes
template <int OUT>
__device__ __forceinline__ void radial_pair(const SWQ& sw, int p, const u64* W3, const u64* b3,
                                            u64 va, u64 vb, u64 vc, u64* R) {
    u64 h[16];
#pragma unroll
    for (int j = 0; j < 16; j++) h[j] = sw.b1[p][j];
#pragma unroll
    for (int j = 0; j < 16; j++) h[j] = fma2(va, sw.W1[p][0][j], h[j]);
#pragma unroll
    for (int j = 0; j < 16; j++) h[j] = fma2(vb, sw.W1[p][1][j], h[j]);
#pragma unroll
    for (int j = 0; j < 16; j++) h[j] = fma2(vc, sw.W1[p][2][j], h[j]);
    ln_relu_pk(h, sw.g1[p], sw.be1[p]);

    u64 acc[16];
#pragma unroll
    for (int j = 0; j < 16; j++) acc[j] = sw.b2[p][j];
#pragma unroll
    for (int k = 0; k < 16; k++) {
#pragma unroll
        for (int j = 0; j < 16; j++)
            acc[j] = fma2(h[k], sw.W2[p][k][j], acc[j]);
    }
    ln_relu_pk(acc, sw.g2[p], sw.be2[p]);

#pragma unroll
    for (int o = 0; o < OUT; o++) R[o] = b3[o];
#pragma unroll
    for (int k = 0; k < 16; k++) {
#pragma unroll
        for (int o = 0; o < OUT; o++)
            R[o] = fma2(acc[k], W3[k * OUT + o], R[o]);
    }
}

__device__ __forceinline__ void atomicMaxF(float* addr, float val) {
    if (val >= 0.f) atomicMax((int*)addr, __float_as_int(val));
    else            atomicMin((unsigned int*)addr, __float_as_uint(val));
}

__global__ void init_kernel() {
    int n = blockIdx.x * blockDim.x + threadIdx.x;
    if (n < N_NODES) {
        g_m[n] = -INFINITY;
        g_s[n] = 0.f;
    }
}

__global__ __launch_bounds__(128, 4) void edge_kernel(
    const float* __restrict__ f0, const float* __restrict__ f1,
    const float* __restrict__ dist,
    const int* __restrict__ u, const int* __restrict__ v,
    const float* __restrict__ wq,
    const float* __restrict__ wj00, const float* __restrict__ wj01,
    const float* __restrict__ wj10, const float* __restrict__ wj11,
    const float* __restrict__ rW1, const float* __restrict__ rb1,
    const float* __restrict__ g1, const float* __restrict__ be1,
    const float* __restrict__ rW2, const float* __restrict__ rb2,
    const float* __restrict__ g2, const float* __restrict__ be2,
    const float* __restrict__ W3_00, const float* __restrict__ b3_00,
    const float* __restrict__ W3_01, const float* __restrict__ b3_01,
    const float* __restrict__ W3_10, const float* __restrict__ b3_10,
    const float* __restrict__ W3_11, const float* __restrict__ b3_11)
{
    __shared__ SWQ sw;
    __shared__ float wj11s[128 * WJPITCH];   // 128 edges/block
    {
        int t = threadIdx.x;
        // pack MLP pairs: idx -> p = idx / per, r = idx % per
        for (int i = t; i < 96; i += 128) {          // W1: 2 pairs x 48
            int p = i / 48, r = i - p * 48;
            ((u64*)sw.W1)[i] = pk(rW1[(2 * p) * 48 + r], rW1[(2 * p + 1) * 48 + r]);
        }
        for (int i = t; i < 32; i += 128) {          // b1/g1/be1: 2 x 16
            int p = i / 16, j = i - p * 16;
            ((u64*)sw.b1)[i]  = pk(rb1[(2 * p) * 16 + j], rb1[(2 * p + 1) * 16 + j]);
            ((u64*)sw.g1)[i]  = pk(g1[(2 * p) * 16 + j],  g1[(2 * p + 1) * 16 + j]);
            ((u64*)sw.be1)[i] = pk(be1[(2 * p) * 16 + j], be1[(2 * p + 1) * 16 + j]);
            ((u64*)sw.b2)[i]  = pk(rb2[(2 * p) * 16 + j], rb2[(2 * p + 1) * 16 + j]);
            ((u64*)sw.g2)[i]  = pk(g2[(2 * p) * 16 + j],  g2[(2 * p + 1) * 16 + j]);
            ((u64*)sw.be2)[i] = pk(be2[(2 * p) * 16 + j], be2[(2 * p + 1) * 16 + j]);
        }
        for (int i = t; i < 512; i += 128) {         // W2: 2 pairs x 256
            int p = i / 256, r = i - p * 256;
            ((u64*)sw.W2)[i] = pk(rW2[(2 * p) * 256 + r], rW2[(2 * p + 1) * 256 + r]);
        }
        for (int i = t; i < 64; i += 128)            // W3 pair 0: (W3_00, W3_01)
            ((u64*)sw.W3p0)[i] = pk(W3_00[i], W3_01[i]);
        for (int i = t; i < 4; i += 128)
            sw.b3p0[i] = pk(b3_00[i], b3_01[i]);
        for (int i = t; i < 192; i += 128) {         // W3 pair 1: (W3_10|0, W3_11)
            int k = i / 12, o = i - k * 12;
            float lo = (o < 4) ? W3_10[k * 4 + o] : 0.f;
            ((u64*)sw.W3p1)[i] = pk(lo, W3_11[k * 12 + o]);
        }
        for (int i = t; i < 12; i += 128)
            sw.b3p1[i] = pk((i < 4) ? b3_10[i] : 0.f, b3_11[i]);
        for (int i = t; i < 8; i += 128) sw.wqs[i] = wq[i];

        // coalesced staging of this block's wj11 slab: edges [128b, 128b+128)
        const float* src = wj11 + (long long)blockIdx.x * 128 * 27;
#pragma unroll
        for (int k = 0; k < 27; k++) {
            int i = t + 128 * k;                     // 0 .. 3455
            int e = i / 27, j = i - e * 27;
            wj11s[e * WJPITCH + j] = src[i];
        }
    }
    __syncthreads();

    int e = blockIdx.x * 128 + threadIdx.x;          // one edge per thread

    int uu = u[e], vv = v[e];
    float2 fu = ((const float2*)f0)[uu];
    float2 fv = ((const float2*)f0)[vv];
    float f1v[6];
    {
        const float2* p0 = (const float2*)f1 + 3 * vv;
        float2 x;
        x = p0[0]; f1v[0] = x.x; f1v[1] = x.y;
        x = p0[1]; f1v[2] = x.x; f1v[3] = x.y;
        x = p0[2]; f1v[4] = x.x; f1v[5] = x.y;
    }

    float v0 = fu.x * fv.x;
    float v1 = fu.y * fv.y;
    float v2 = dist[e];
    u64 va = pk(v0, v0), vb = pk(v1, v1), vc = pk(v2, v2);

    float k00, k01;            // l=0 accumulators per o
    float k1[2][3];            // [o][l]

    // ==== pair 0: MLP0 (l=0,k=0) lo, MLP1 (l=0,k=1) hi ====
    {
        u64 R[4];
        radial_pair<4>(sw, 0, (const u64*)sw.W3p0, sw.b3p0, va, vb, vc, R);
        float2 r0 = upk2(R[0]), r1 = upk2(R[1]), r2 = upk2(R[2]), r3 = upk2(R[3]);
        float wj00e = wj00[e];
        k00 = wj00e * fmaf(r0.x, fv.x, r1.x * fv.y);
        k01 = wj00e * fmaf(r2.x, fv.x, r3.x * fv.y);
        float w0 = wj01[3 * e + 0], w1 = wj01[3 * e + 1], w2 = wj01[3 * e + 2];
        float t0 = fmaf(w0, f1v[0], fmaf(w1, f1v[1], w2 * f1v[2]));
        float t1 = fmaf(w0, f1v[3], fmaf(w1, f1v[4], w2 * f1v[5]));
        k00 = fmaf(r0.y, t0, fmaf(r1.y, t1, k00));
        k01 = fmaf(r2.y, t0, fmaf(r3.y, t1, k01));
    }

    // ==== pair 1: MLP2 (l=1,k=0) lo, MLP3 (l=1,k=1) hi ====
    {
        u64 R[12];
        radial_pair<12>(sw, 1, (const u64*)sw.W3p1, sw.b3p1, va, vb, vc, R);
        // MLP2 (lo of R[0..3])
        {
            float2 r0 = upk2(R[0]), r1 = upk2(R[1]), r2 = upk2(R[2]), r3 = upk2(R[3]);
            float d0 = fmaf(r0.x, fv.x, r1.x * fv.y);
            float d1 = fmaf(r2.x, fv.x, r3.x * fv.y);
#pragma unroll
            for (int l = 0; l < 3; l++) {
                float w = wj10[3 * e + l];
                k1[0][l] = d0 * w;
                k1[1][l] = d1 * w;
            }
        }
        // MLP3 (hi of R[0..11]); R3 index [j][o][i] = 4j+2o+i
        const float* wr = &wj11s[threadIdx.x * WJPITCH];
#pragma unroll
        for (int j = 0; j < 3; j++) {
            float r0 = upk2(R[4 * j + 0]).y;
            float r1 = upk2(R[4 * j + 1]).y;
            float r2 = upk2(R[4 * j + 2]).y;
            float r3 = upk2(R[4 * j + 3]).y;
#pragma unroll
            for (int l = 0; l < 3; l++) {
                float w0 = wr[9 * j + 3 * l], w1 = wr[9 * j + 3 * l + 1], w2 = wr[9 * j + 3 * l + 2];
                float s0 = fmaf(w0, f1v[0], fmaf(w1, f1v[1], w2 * f1v[2]));
                float s1 = fmaf(w0, f1v[3], fmaf(w1, f1v[4], w2 * f1v[5]));
                k1[0][l] = fmaf(r0, s0, fmaf(r1, s1, k1[0][l]));
                k1[1][l] = fmaf(r2, s0, fmaf(r3, s1, k1[1][l]));
            }
        }
    }

    // ---- q·k dot, store, atomicMax ----
    float dot = 0.f;
#pragma unroll
    for (int o = 0; o < 2; o++) {
        float q0 = fmaf(sw.wqs[o * 2 + 0], fv.x, sw.wqs[o * 2 + 1] * fv.y);
        dot = fmaf(q0, (o == 0 ? k00 : k01), dot);
#pragma unroll
        for (int m = 0; m < 3; m++) {
            float q1 = fmaf(sw.wqs[4 + o * 2 + 0], f1v[m], sw.wqs[4 + o * 2 + 1] * f1v[3 + m]);
            dot = fmaf(q1, k1[o][m], dot);
        }
    }

    g_dot[e] = dot;
    atomicMaxF(&g_m[vv], dot);
}

__global__ void exp_kernel(const int* __restrict__ v, float* __restrict__ out) {
    int e = blockIdx.x * 256 + threadIdx.x;
    if (e >= N_EDGES) return;
    int vv = v[e];
    float p = __expf(g_dot[e] - g_m[vv]);
    out[e] = p;
    atomicAdd(&g_s[vv], p);
}

__global__ void norm_kernel(const int* __restrict__ v, float* __restrict__ out) {
    int t = blockIdx.x * 256 + threadIdx.x;
    if (t >= HALF_E) return;
    int2 vv = ((const int2*)v)[t];
    float2 o = ((const float2*)out)[t];
    o.x = o.x / g_s[vv.x];
    o.y = o.y / g_s[vv.y];
    ((float2*)out)[t] = o;
}

extern "C" void kernel_launch(void* const* d_in, const int* in_sizes, int n_in,
                              void* d_out, int out_size) {
    const float* f0    = (const float*)d_in[0];
    const float* f1    = (const float*)d_in[1];
    const float* dist  = (const float*)d_in[2];
    const int*   u     = (const int*)d_in[3];
    const int*   v     = (const int*)d_in[4];
    const float* wq    = (const float*)d_in[5];
    const float* wj00  = (const float*)d_in[6];
    const float* wj01  = (const float*)d_in[7];
    const float* wj10  = (const float*)d_in[8];
    const float* wj11  = (const float*)d_in[9];
    const float* rW1   = (const float*)d_in[10];
    const float* rb1   = (const float*)d_in[11];
    const float* g1    = (const float*)d_in[12];
    const float* be1   = (const float*)d_in[13];
    const float* rW2   = (const float*)d_in[14];
    const float* rb2   = (const float*)d_in[15];
    const float* g2    = (const float*)d_in[16];
    const float* be2   = (const float*)d_in[17];
    const float* W3_00 = (const float*)d_in[18];
    const float* b3_00 = (const float*)d_in[19];
    const float* W3_01 = (const float*)d_in[20];
    const float* b3_01 = (const float*)d_in[21];
    const float* W3_10 = (const float*)d_in[22];
    const float* b3_10 = (const float*)d_in[23];
    const float* W3_11 = (const float*)d_in[24];
    const float* b3_11 = (const float*)d_in[25];
    float* out = (float*)d_out;

    init_kernel<<<(N_NODES + 255) / 256, 256>>>();
    edge_kernel<<<N_EDGES / 128, 128>>>(
        f0, f1, dist, u, v, wq, wj00, wj01, wj10, wj11,
        rW1, rb1, g1, be1, rW2, rb2, g2, be2,
        W3_00, b3_00, W3_01, b3_01, W3_10, b3_10, W3_11, b3_11);
    exp_kernel<<<(N_EDGES + 255) / 256, 256>>>(v, out);
    norm_kernel<<<HALF_E / 256, 256>>>(v, out);
}

// round 12
// speedup vs baseline: 1.0408x; 1.0013x over previous
#include <cuda_runtime.h>
#include <math.h>

#define N_NODES 100000
#define N_EDGES 1600000
#define HALF_E  (N_EDGES / 2)
#define WJPITCH 29

typedef unsigned long long u64;

__device__ float g_dot[N_EDGES];
__device__ float g_m[N_NODES];
__device__ float g_s[N_NODES];

// ---- packed f32x2 helpers ----
union PU { u64 u; float2 f; };

__device__ __forceinline__ u64 pk(float lo, float hi) {
    PU p; p.f.x = lo; p.f.y = hi; return p.u;
}
__device__ __forceinline__ float2 upk2(u64 x) { PU p; p.u = x; return p.f; }

__device__ __forceinline__ u64 fma2(u64 a, u64 b, u64 c) {
    u64 d; asm("fma.rn.f32x2 %0,%1,%2,%3;" : "=l"(d) : "l"(a), "l"(b), "l"(c)); return d;
}
__device__ __forceinline__ u64 add2(u64 a, u64 b) {
    u64 d; asm("add.rn.f32x2 %0,%1,%2;" : "=l"(d) : "l"(a), "l"(b)); return d;
}
__device__ __forceinline__ u64 mul2(u64 a, u64 b) {
    u64 d; asm("mul.rn.f32x2 %0,%1,%2;" : "=l"(d) : "l"(a), "l"(b)); return d;
}

#define C_NEG1      0xBF800000BF800000ull   // (-1.f, -1.f)
#define C_SIXTEENTH 0x3D8000003D800000ull   // (0.0625f, 0.0625f)

// weights packed across MLP PAIRS: lane lo = MLP 2p, lane hi = MLP 2p+1
struct SWQ {
    u64 W1[2][3][16];
    u64 b1[2][16], g1[2][16], be1[2][16];
    u64 W2[2][16][16];
    u64 b2[2][16], g2[2][16], be2[2][16];
    u64 W3p0[16][4];    // (W3_00, W3_01)
    u64 b3p0[4];
    u64 W3p1[16][12];   // o<4: (W3_10, W3_11); o>=4: (0, W3_11)
    u64 b3p1[12];
    float wqs[8];
};

// packed LN (each lane an independent LN): subtract-mean-then-square (safe)
__device__ __forceinline__ void ln_relu_pk(u64* h, const u64* g, const u64* be) {
    u64 s = h[0];
#pragma unroll
    for (int j = 1; j < 16; j++) s = add2(s, h[j]);
    u64 mu = mul2(s, C_SIXTEENTH);
    u64 vs = 0ull;
#pragma unroll
    for (int j = 0; j < 16; j++) {
        h[j] = fma2(mu, C_NEG1, h[j]);
        vs = fma2(h[j], h[j], vs);
    }
    float2 V = upk2(vs);
    u64 inv = pk(rsqrtf(fmaf(V.x, 0.0625f, 1e-5f)),
                 rsqrtf(fmaf(V.y, 0.0625f, 1e-5f)));
#pragma unroll
    for (int j = 0; j < 16; j++) {
        u64 tj = mul2(h[j], inv);
        PU val; val.u = fma2(tj, g[j], be[j]);
        val.f.x = fmaxf(val.f.x, 0.f);
        val.f.y = fmaxf(val.f.y, 0.f);
        h[j] = val.u;
    }
}

// one packed radial covering MLP pair p; input identical in both lanes
template <int OUT>
__device__ __forceinline__ void radial_pair(const SWQ& sw, int p, const u64* W3, const u64* b3,
                                            u64 va, u64 vb, u64 vc, u64* R) {
    u64 h[16];
#pragma unroll
    for (int j = 0; j < 16; j++) h[j] = sw.b1[p][j];
#pragma unroll
    for (int j = 0; j < 16; j++) h[j] = fma2(va, sw.W1[p][0][j], h[j]);
#pragma unroll
    for (int j = 0; j < 16; j++) h[j] = fma2(vb, sw.W1[p][1][j], h[j]);
#pragma unroll
    for (int j = 0; j < 16; j++) h[j] = fma2(vc, sw.W1[p][2][j], h[j]);
    ln_relu_pk(h, sw.g1[p], sw.be1[p]);

    u64 acc[16];
#pragma unroll
    for (int j = 0; j < 16; j++) acc[j] = sw.b2[p][j];
#pragma unroll
    for (int k = 0; k < 16; k++) {
#pragma unroll
        for (int j = 0; j < 16; j++)
            acc[j] = fma2(h[k], sw.W2[p][k][j], acc[j]);
    }
    ln_relu_pk(acc, sw.g2[p], sw.be2[p]);

#pragma unroll
    for (int o = 0; o < OUT; o++) R[o] = b3[o];
#pragma unroll
    for (int k = 0; k < 16; k++) {
#pragma unroll
        for (int o = 0; o < OUT; o++)
            R[o] = fma2(acc[k], W3[k * OUT + o], R[o]);
    }
}

__device__ __forceinline__ void atomicMaxF(float* addr, float val) {
    if (val >= 0.f) atomicMax((int*)addr, __float_as_int(val));
    else            atomicMin((unsigned int*)addr, __float_as_uint(val));
}

__global__ void init_kernel() {
    int n = blockIdx.x * blockDim.x + threadIdx.x;
    if (n < N_NODES) {
        g_m[n] = -INFINITY;
        g_s[n] = 0.f;
    }
}

__global__ __launch_bounds__(128, 4) void edge_kernel(
    const float* __restrict__ f0, const float* __restrict__ f1,
    const float* __restrict__ dist,
    const int* __restrict__ u, const int* __restrict__ v,
    const float* __restrict__ wq,
    const float* __restrict__ wj00, const float* __restrict__ wj01,
    const float* __restrict__ wj10, const float* __restrict__ wj11,
    const float* __restrict__ rW1, const float* __restrict__ rb1,
    const float* __restrict__ g1, const float* __restrict__ be1,
    const float* __restrict__ rW2, const float* __restrict__ rb2,
    const float* __restrict__ g2, const float* __restrict__ be2,
    const float* __restrict__ W3_00, const float* __restrict__ b3_00,
    const float* __restrict__ W3_01, const float* __restrict__ b3_01,
    const float* __restrict__ W3_10, const float* __restrict__ b3_10,
    const float* __restrict__ W3_11, const float* __restrict__ b3_11)
{
    __shared__ SWQ sw;
    __shared__ float wj11s[128 * WJPITCH];   // 128 edges/block
    {
        int t = threadIdx.x;
        // pack MLP pairs: idx -> p = idx / per, r = idx % per
        for (int i = t; i < 96; i += 128) {          // W1: 2 pairs x 48
            int p = i / 48, r = i - p * 48;
            ((u64*)sw.W1)[i] = pk(rW1[(2 * p) * 48 + r], rW1[(2 * p + 1) * 48 + r]);
        }
        for (int i = t; i < 32; i += 128) {          // b1/g1/be1: 2 x 16
            int p = i / 16, j = i - p * 16;
            ((u64*)sw.b1)[i]  = pk(rb1[(2 * p) * 16 + j], rb1[(2 * p + 1) * 16 + j]);
            ((u64*)sw.g1)[i]  = pk(g1[(2 * p) * 16 + j],  g1[(2 * p + 1) * 16 + j]);
            ((u64*)sw.be1)[i] = pk(be1[(2 * p) * 16 + j], be1[(2 * p + 1) * 16 + j]);
            ((u64*)sw.b2)[i]  = pk(rb2[(2 * p) * 16 + j], rb2[(2 * p + 1) * 16 + j]);
            ((u64*)sw.g2)[i]  = pk(g2[(2 * p) * 16 + j],  g2[(2 * p + 1) * 16 + j]);
            ((u64*)sw.be2)[i] = pk(be2[(2 * p) * 16 + j], be2[(2 * p + 1) * 16 + j]);
        }
        for (int i = t; i < 512; i += 128) {         // W2: 2 pairs x 256
            int p = i / 256, r = i - p * 256;
            ((u64*)sw.W2)[i] = pk(rW2[(2 * p) * 256 + r], rW2[(2 * p + 1) * 256 + r]);
        }
        for (int i = t; i < 64; i += 128)            // W3 pair 0: (W3_00, W3_01)
            ((u64*)sw.W3p0)[i] = pk(W3_00[i], W3_01[i]);
        for (int i = t; i < 4; i += 128)
            sw.b3p0[i] = pk(b3_00[i], b3_01[i]);
        for (int i = t; i < 192; i += 128) {         // W3 pair 1: (W3_10|0, W3_11)
            int k = i / 12, o = i - k * 12;
            float lo = (o < 4) ? W3_10[k * 4 + o] : 0.f;
            ((u64*)sw.W3p1)[i] = pk(lo, W3_11[k * 12 + o]);
        }
        for (int i = t; i < 12; i += 128)
            sw.b3p1[i] = pk((i < 4) ? b3_10[i] : 0.f, b3_11[i]);
        for (int i = t; i < 8; i += 128) sw.wqs[i] = wq[i];

        // coalesced staging of this block's wj11 slab: edges [128b, 128b+128)
        const float* src = wj11 + (long long)blockIdx.x * 128 * 27;
#pragma unroll
        for (int k = 0; k < 27; k++) {
            int i = t + 128 * k;                     // 0 .. 3455
            int e = i / 27, j = i - e * 27;
            wj11s[e * WJPITCH + j] = src[i];
        }
    }
    __syncthreads();

    int e = blockIdx.x * 128 + threadIdx.x;          // one edge per thread

    int uu = u[e], vv = v[e];
    float2 fu = ((const float2*)f0)[uu];
    float2 fv = ((const float2*)f0)[vv];
    float f1v[6];
    {
        const float2* p0 = (const float2*)f1 + 3 * vv;
        float2 x;
        x = p0[0]; f1v[0] = x.x; f1v[1] = x.y;
        x = p0[1]; f1v[2] = x.x; f1v[3] = x.y;
        x = p0[2]; f1v[4] = x.x; f1v[5] = x.y;
    }

    float v0 = fu.x * fv.x;
    float v1 = fu.y * fv.y;
    float v2 = dist[e];
    u64 va = pk(v0, v0), vb = pk(v1, v1), vc = pk(v2, v2);

    float k00, k01;            // l=0 accumulators per o
    float k1[2][3];            // [o][l]

    // ==== pair 0: MLP0 (l=0,k=0) lo, MLP1 (l=0,k=1) hi ====
    {
        u64 R[4];
        radial_pair<4>(sw, 0, (const u64*)sw.W3p0, sw.b3p0, va, vb, vc, R);
        float2 r0 = upk2(R[0]), r1 = upk2(R[1]), r2 = upk2(R[2]), r3 = upk2(R[3]);
        float wj00e = wj00[e];
        k00 = wj00e * fmaf(r0.x, fv.x, r1.x * fv.y);
        k01 = wj00e * fmaf(r2.x, fv.x, r3.x * fv.y);
        float w0 = wj01[3 * e + 0], w1 = wj01[3 * e + 1], w2 = wj01[3 * e + 2];
        float t0 = fmaf(w0, f1v[0], fmaf(w1, f1v[1], w2 * f1v[2]));
        float t1 = fmaf(w0, f1v[3], fmaf(w1, f1v[4], w2 * f1v[5]));
        k00 = fmaf(r0.y, t0, fmaf(r1.y, t1, k00));
        k01 = fmaf(r2.y, t0, fmaf(r3.y, t1, k01));
    }

    // ==== pair 1: MLP2 (l=1,k=0) lo, MLP3 (l=1,k=1) hi ====
    {
        u64 R[12];
        radial_pair<12>(sw, 1, (const u64*)sw.W3p1, sw.b3p1, va, vb, vc, R);
        // MLP2 (lo of R[0..3])
        {
            float2 r0 = upk2(R[0]), r1 = upk2(R[1]), r2 = upk2(R[2]), r3 = upk2(R[3]);
            float d0 = fmaf(r0.x, fv.x, r1.x * fv.y);
            float d1 = fmaf(r2.x, fv.x, r3.x * fv.y);
#pragma unroll
            for (int l = 0; l < 3; l++) {
                float w = wj10[3 * e + l];
                k1[0][l] = d0 * w;
                k1[1][l] = d1 * w;
            }
        }
        // MLP3 (hi of R[0..11]); R3 index [j][o][i] = 4j+2o+i
        const float* wr = &wj11s[threadIdx.x * WJPITCH];
#pragma unroll
        for (int j = 0; j < 3; j++) {
            float r0 = upk2(R[4 * j + 0]).y;
            float r1 = upk2(R[4 * j + 1]).y;
            float r2 = upk2(R[4 * j + 2]).y;
            float r3 = upk2(R[4 * j + 3]).y;
#pragma unroll
            for (int l = 0; l < 3; l++) {
                float w0 = wr[9 * j + 3 * l], w1 = wr[9 * j + 3 * l + 1], w2 = wr[9 * j + 3 * l + 2];
                float s0 = fmaf(w0, f1v[0], fmaf(w1, f1v[1], w2 * f1v[2]));
                float s1 = fmaf(w0, f1v[3], fmaf(w1, f1v[4], w2 * f1v[5]));
                k1[0][l] = fmaf(r0, s0, fmaf(r1, s1, k1[0][l]));
                k1[1][l] = fmaf(r2, s0, fmaf(r3, s1, k1[1][l]));
            }
        }
    }

    // ---- q·k dot, store, atomicMax ----
    float dot = 0.f;
#pragma unroll
    for (int o = 0; o < 2; o++) {
        float q0 = fmaf(sw.wqs[o * 2 + 0], fv.x, sw.wqs[o * 2 + 1] * fv.y);
        dot = fmaf(q0, (o == 0 ? k00 : k01), dot);
#pragma unroll
        for (int m = 0; m < 3; m++) {
            float q1 = fmaf(sw.wqs[4 + o * 2 + 0], f1v[m], sw.wqs[4 + o * 2 + 1] * f1v[3 + m]);
            dot = fmaf(q1, k1[o][m], dot);
        }
    }

    g_dot[e] = dot;
    atomicMaxF(&g_m[vv], dot);
}

__global__ void exp_kernel(const int* __restrict__ v, float* __restrict__ out) {
    int e = blockIdx.x * 256 + threadIdx.x;
    if (e >= N_EDGES) return;
    int vv = v[e];
    float p = __expf(g_dot[e] - g_m[vv]);
    out[e] = p;
    atomicAdd(&g_s[vv], p);
}

__global__ void norm_kernel(const int* __restrict__ v, float* __restrict__ out) {
    int t = blockIdx.x * 256 + threadIdx.x;
    if (t >= HALF_E) return;
    int2 vv = ((const int2*)v)[t];
    float2 o = ((const float2*)out)[t];
    o.x = o.x / g_s[vv.x];
    o.y = o.y / g_s[vv.y];
    ((float2*)out)[t] = o;
}

extern "C" void kernel_launch(void* const* d_in, const int* in_sizes, int n_in,
                              void* d_out, int out_size) {
    const float* f0    = (const float*)d_in[0];
    const float* f1    = (const float*)d_in[1];
    const float* dist  = (const float*)d_in[2];
    const int*   u     = (const int*)d_in[3];
    const int*   v     = (const int*)d_in[4];
    const float* wq    = (const float*)d_in[5];
    const float* wj00  = (const float*)d_in[6];
    const float* wj01  = (const float*)d_in[7];
    const float* wj10  = (const float*)d_in[8];
    const float* wj11  = (const float*)d_in[9];
    const float* rW1   = (const float*)d_in[10];
    const float* rb1   = (const float*)d_in[11];
    const float* g1    = (const float*)d_in[12];
    const float* be1   = (const float*)d_in[13];
    const float* rW2   = (const float*)d_in[14];
    const float* rb2   = (const float*)d_in[15];
    const float* g2    = (const float*)d_in[16];
    const float* be2   = (const float*)d_in[17];
    const float* W3_00 = (const float*)d_in[18];
    const float* b3_00 = (const float*)d_in[19];
    const float* W3_01 = (const float*)d_in[20];
    const float* b3_01 = (const float*)d_in[21];
    const float* W3_10 = (const float*)d_in[22];
    const float* b3_10 = (const float*)d_in[23];
    const float* W3_11 = (const float*)d_in[24];
    const float* b3_11 = (const float*)d_in[25];
    float* out = (float*)d_out;

    init_kernel<<<(N_NODES + 255) / 256, 256>>>();
    edge_kernel<<<N_EDGES / 128, 128>>>(
        f0, f1, dist, u, v, wq, wj00, wj01, wj10, wj11,
        rW1, rb1, g1, be1, rW2, rb2, g2, be2,
        W3_00, b3_00, W3_01, b3_01, W3_10, b3_10, W3_11, b3_11);
    exp_kernel<<<(N_EDGES + 255) / 256, 256>>>(v, out);
    norm_kernel<<<HALF_E / 256, 256>>>(v, out);
}

// round 13
// speedup vs baseline: 1.0411x; 1.0003x over previous
#include <cuda_runtime.h>
#include <math.h>

#define N_NODES 100000
#define N_EDGES 1600000
#define HALF_E  (N_EDGES / 2)
#define WJPITCH 29

typedef unsigned long long u64;

__device__ float g_dot[N_EDGES];
__device__ float g_m[N_NODES];
__device__ float g_s[N_NODES];

// ---- packed f32x2 helpers ----
union PU { u64 u; float2 f; };

__device__ __forceinline__ u64 pk(float lo, float hi) {
    PU p; p.f.x = lo; p.f.y = hi; return p.u;
}
__device__ __forceinline__ float2 upk2(u64 x) { PU p; p.u = x; return p.f; }

__device__ __forceinline__ u64 fma2(u64 a, u64 b, u64 c) {
    u64 d; asm("fma.rn.f32x2 %0,%1,%2,%3;" : "=l"(d) : "l"(a), "l"(b), "l"(c)); return d;
}
__device__ __forceinline__ u64 add2(u64 a, u64 b) {
    u64 d; asm("add.rn.f32x2 %0,%1,%2;" : "=l"(d) : "l"(a), "l"(b)); return d;
}
__device__ __forceinline__ u64 mul2(u64 a, u64 b) {
    u64 d; asm("mul.rn.f32x2 %0,%1,%2;" : "=l"(d) : "l"(a), "l"(b)); return d;
}

// weights packed across MLP PAIRS: lane lo = MLP 2p, lane hi = MLP 2p+1
struct SWQ {
    u64 W1[2][3][16];
    u64 b1[2][16], g1[2][16], be1[2][16];
    u64 W2[2][16][16];
    u64 b2[2][16], g2[2][16], be2[2][16];
    u64 W3p0[16][4];    // (W3_00, W3_01)
    u64 b3p0[4];
    u64 W3p1[16][12];   // o<4: (W3_10, W3_11); o>=4: (0, W3_11)
    u64 b3p1[12];
    float wqs[8];
};

// one-pass LN with tree reductions + guarded variance (clamped E[h^2]-mu^2), then ReLU
__device__ __forceinline__ void ln_relu_pk(u64* h, const u64* g, const u64* be) {
    // parallel tree: sum of h
    u64 a0 = add2(h[0], h[1]),  a1 = add2(h[2], h[3]);
    u64 a2 = add2(h[4], h[5]),  a3 = add2(h[6], h[7]);
    u64 a4 = add2(h[8], h[9]),  a5 = add2(h[10], h[11]);
    u64 a6 = add2(h[12], h[13]), a7 = add2(h[14], h[15]);
    a0 = add2(a0, a1); a2 = add2(a2, a3); a4 = add2(a4, a5); a6 = add2(a6, a7);
    a0 = add2(a0, a2); a4 = add2(a4, a6);
    u64 s = add2(a0, a4);
    // parallel tree: sum of h^2
    u64 q0 = mul2(h[0], h[0]);
    q0 = fma2(h[1], h[1], q0);
    u64 q1 = mul2(h[2], h[2]);  q1 = fma2(h[3], h[3], q1);
    u64 q2 = mul2(h[4], h[4]);  q2 = fma2(h[5], h[5], q2);
    u64 q3 = mul2(h[6], h[6]);  q3 = fma2(h[7], h[7], q3);
    u64 q4 = mul2(h[8], h[8]);  q4 = fma2(h[9], h[9], q4);
    u64 q5 = mul2(h[10], h[10]); q5 = fma2(h[11], h[11], q5);
    u64 q6 = mul2(h[12], h[12]); q6 = fma2(h[13], h[13], q6);
    u64 q7 = mul2(h[14], h[14]); q7 = fma2(h[15], h[15], q7);
    q0 = add2(q0, q1); q2 = add2(q2, q3); q4 = add2(q4, q5); q6 = add2(q6, q7);
    q0 = add2(q0, q2); q4 = add2(q4, q6);
    u64 s2 = add2(q0, q4);

    float2 S = upk2(s), Q = upk2(s2);
    float mu0 = S.x * 0.0625f, mu1 = S.y * 0.0625f;
    float var0 = fmaxf(fmaf(-mu0, mu0, Q.x * 0.0625f), 0.f);
    float var1 = fmaxf(fmaf(-mu1, mu1, Q.y * 0.0625f), 0.f);
    float inv0 = rsqrtf(var0 + 1e-5f);
    float inv1 = rsqrtf(var1 + 1e-5f);
    u64 invb = pk(inv0, inv1);
    u64 nmi  = pk(-mu0 * inv0, -mu1 * inv1);
#pragma unroll
    for (int j = 0; j < 16; j++) {
        u64 tj = mul2(invb, g[j]);
        u64 cj = fma2(nmi, g[j], be[j]);
        PU val; val.u = fma2(h[j], tj, cj);
        val.f.x = fmaxf(val.f.x, 0.f);
        val.f.y = fmaxf(val.f.y, 0.f);
        h[j] = val.u;
    }
}

// one packed radial covering MLP pair p; input identical in both lanes
template <int OUT>
__device__ __forceinline__ void radial_pair(const SWQ& sw, int p, const u64* W3, const u64* b3,
                                            u64 va, u64 vb, u64 vc, u64* R) {
    u64 h[16];
#pragma unroll
    for (int j = 0; j < 16; j++) h[j] = sw.b1[p][j];
#pragma unroll
    for (int j = 0; j < 16; j++) h[j] = fma2(va, sw.W1[p][0][j], h[j]);
#pragma unroll
    for (int j = 0; j < 16; j++) h[j] = fma2(vb, sw.W1[p][1][j], h[j]);
#pragma unroll
    for (int j = 0; j < 16; j++) h[j] = fma2(vc, sw.W1[p][2][j], h[j]);
    ln_relu_pk(h, sw.g1[p], sw.be1[p]);

    u64 acc[16];
#pragma unroll
    for (int j = 0; j < 16; j++) acc[j] = sw.b2[p][j];
#pragma unroll
    for (int k = 0; k < 16; k++) {
#pragma unroll
        for (int j = 0; j < 16; j++)
            acc[j] = fma2(h[k], sw.W2[p][k][j], acc[j]);
    }
    ln_relu_pk(acc, sw.g2[p], sw.be2[p]);

#pragma unroll
    for (int o = 0; o < OUT; o++) R[o] = b3[o];
#pragma unroll
    for (int k = 0; k < 16; k++) {
#pragma unroll
        for (int o = 0; o < OUT; o++)
            R[o] = fma2(acc[k], W3[k * OUT + o], R[o]);
    }
}

__device__ __forceinline__ void atomicMaxF(float* addr, float val) {
    if (val >= 0.f) atomicMax((int*)addr, __float_as_int(val));
    else            atomicMin((unsigned int*)addr, __float_as_uint(val));
}

__global__ void init_kernel() {
    int n = blockIdx.x * blockDim.x + threadIdx.x;
    if (n < N_NODES) {
        g_m[n] = -INFINITY;
        g_s[n] = 0.f;
    }
}

__global__ __launch_bounds__(128, 4) void edge_kernel(
    const float* __restrict__ f0, const float* __restrict__ f1,
    const float* __restrict__ dist,
    const int* __restrict__ u, const int* __restrict__ v,
    const float* __restrict__ wq,
    const float* __restrict__ wj00, const float* __restrict__ wj01,
    const float* __restrict__ wj10, const float* __restrict__ wj11,
    const float* __restrict__ rW1, const float* __restrict__ rb1,
    const float* __restrict__ g1, const float* __restrict__ be1,
    const float* __restrict__ rW2, const float* __restrict__ rb2,
    const float* __restrict__ g2, const float* __restrict__ be2,
    const float* __restrict__ W3_00, const float* __restrict__ b3_00,
    const float* __restrict__ W3_01, const float* __restrict__ b3_01,
    const float* __restrict__ W3_10, const float* __restrict__ b3_10,
    const float* __restrict__ W3_11, const float* __restrict__ b3_11)
{
    __shared__ SWQ sw;
    __shared__ float wj11s[128 * WJPITCH];   // 128 edges/block
    {
        int t = threadIdx.x;
        for (int i = t; i < 96; i += 128) {          // W1: 2 pairs x 48
            int p = i / 48, r = i - p * 48;
            ((u64*)sw.W1)[i] = pk(rW1[(2 * p) * 48 + r], rW1[(2 * p + 1) * 48 + r]);
        }
        for (int i = t; i < 32; i += 128) {          // vectors: 2 x 16
            int p = i / 16, j = i - p * 16;
            ((u64*)sw.b1)[i]  = pk(rb1[(2 * p) * 16 + j], rb1[(2 * p + 1) * 16 + j]);
            ((u64*)sw.g1)[i]  = pk(g1[(2 * p) * 16 + j],  g1[(2 * p + 1) * 16 + j]);
            ((u64*)sw.be1)[i] = pk(be1[(2 * p) * 16 + j], be1[(2 * p + 1) * 16 + j]);
            ((u64*)sw.b2)[i]  = pk(rb2[(2 * p) * 16 + j], rb2[(2 * p + 1) * 16 + j]);
            ((u64*)sw.g2)[i]  = pk(g2[(2 * p) * 16 + j],  g2[(2 * p + 1) * 16 + j]);
            ((u64*)sw.be2)[i] = pk(be2[(2 * p) * 16 + j], be2[(2 * p + 1) * 16 + j]);
        }
        for (int i = t; i < 512; i += 128) {         // W2: 2 pairs x 256
            int p = i / 256, r = i - p * 256;
            ((u64*)sw.W2)[i] = pk(rW2[(2 * p) * 256 + r], rW2[(2 * p + 1) * 256 + r]);
        }
        for (int i = t; i < 64; i += 128)
            ((u64*)sw.W3p0)[i] = pk(W3_00[i], W3_01[i]);
        for (int i = t; i < 4; i += 128)
            sw.b3p0[i] = pk(b3_00[i], b3_01[i]);
        for (int i = t; i < 192; i += 128) {
            int k = i / 12, o = i - k * 12;
            float lo = (o < 4) ? W3_10[k * 4 + o] : 0.f;
            ((u64*)sw.W3p1)[i] = pk(lo, W3_11[k * 12 + o]);
        }
        for (int i = t; i < 12; i += 128)
            sw.b3p1[i] = pk((i < 4) ? b3_10[i] : 0.f, b3_11[i]);
        for (int i = t; i < 8; i += 128) sw.wqs[i] = wq[i];

        // coalesced staging of this block's wj11 slab
        const float* src = wj11 + (long long)blockIdx.x * 128 * 27;
#pragma unroll
        for (int k = 0; k < 27; k++) {
            int i = t + 128 * k;
            int e = i / 27, j = i - e * 27;
            wj11s[e * WJPITCH + j] = src[i];
        }
    }
    __syncthreads();

    int e = blockIdx.x * 128 + threadIdx.x;          // one edge per thread

    // ---- hoist ALL per-edge global loads up front ----
    int uu = u[e], vv = v[e];
    float v2 = dist[e];
    float wj00e = wj00[e];
    float wj01v[3], wj10v[3];
#pragma unroll
    for (int m = 0; m < 3; m++) { wj01v[m] = wj01[3 * e + m]; wj10v[m] = wj10[3 * e + m]; }
    float2 fu = ((const float2*)f0)[uu];
    float2 fv = ((const float2*)f0)[vv];
    float f1v[6];
    {
        const float2* p0 = (const float2*)f1 + 3 * vv;
        float2 x;
        x = p0[0]; f1v[0] = x.x; f1v[1] = x.y;
        x = p0[1]; f1v[2] = x.x; f1v[3] = x.y;
        x = p0[2]; f1v[4] = x.x; f1v[5] = x.y;
    }

    float v0 = fu.x * fv.x;
    float v1 = fu.y * fv.y;
    u64 va = pk(v0, v0), vb = pk(v1, v1), vc = pk(v2, v2);

    float k00, k01;            // l=0 accumulators per o
    float k1[2][3];            // [o][l]

    // ==== pair 0: MLP0 (l=0,k=0) lo, MLP1 (l=0,k=1) hi ====
    {
        u64 R[4];
        radial_pair<4>(sw, 0, (const u64*)sw.W3p0, sw.b3p0, va, vb, vc, R);
        float2 r0 = upk2(R[0]), r1 = upk2(R[1]), r2 = upk2(R[2]), r3 = upk2(R[3]);
        k00 = wj00e * fmaf(r0.x, fv.x, r1.x * fv.y);
        k01 = wj00e * fmaf(r2.x, fv.x, r3.x * fv.y);
        float t0 = fmaf(wj01v[0], f1v[0], fmaf(wj01v[1], f1v[1], wj01v[2] * f1v[2]));
        float t1 = fmaf(wj01v[0], f1v[3], fmaf(wj01v[1], f1v[4], wj01v[2] * f1v[5]));
        k00 = fmaf(r0.y, t0, fmaf(r1.y, t1, k00));
        k01 = fmaf(r2.y, t0, fmaf(r3.y, t1, k01));
    }

    // ==== pair 1: MLP2 (l=1,k=0) lo, MLP3 (l=1,k=1) hi ====
    {
        u64 R[12];
        radial_pair<12>(sw, 1, (const u64*)sw.W3p1, sw.b3p1, va, vb, vc, R);
        {
            float2 r0 = upk2(R[0]), r1 = upk2(R[1]), r2 = upk2(R[2]), r3 = upk2(R[3]);
            float d0 = fmaf(r0.x, fv.x, r1.x * fv.y);
            float d1 = fmaf(r2.x, fv.x, r3.x * fv.y);
#pragma unroll
            for (int l = 0; l < 3; l++) {
                k1[0][l] = d0 * wj10v[l];
                k1[1][l] = d1 * wj10v[l];
            }
        }
        const float* wr = &wj11s[threadIdx.x * WJPITCH];
#pragma unroll
        for (int j = 0; j < 3; j++) {
            float r0 = upk2(R[4 * j + 0]).y;
            float r1 = upk2(R[4 * j + 1]).y;
            float r2 = upk2(R[4 * j + 2]).y;
            float r3 = upk2(R[4 * j + 3]).y;
#pragma unroll
            for (int l = 0; l < 3; l++) {
                float w0 = wr[9 * j + 3 * l], w1 = wr[9 * j + 3 * l + 1], w2 = wr[9 * j + 3 * l + 2];
                float s0 = fmaf(w0, f1v[0], fmaf(w1, f1v[1], w2 * f1v[2]));
                float s1 = fmaf(w0, f1v[3], fmaf(w1, f1v[4], w2 * f1v[5]));
                k1[0][l] = fmaf(r0, s0, fmaf(r1, s1, k1[0][l]));
                k1[1][l] = fmaf(r2, s0, fmaf(r3, s1, k1[1][l]));
            }
        }
    }

    // ---- q·k dot, store, atomicMax ----
    float dot = 0.f;
#pragma unroll
    for (int o = 0; o < 2; o++) {
        float q0 = fmaf(sw.wqs[o * 2 + 0], fv.x, sw.wqs[o * 2 + 1] * fv.y);
        dot = fmaf(q0, (o == 0 ? k00 : k01), dot);
#pragma unroll
        for (int m = 0; m < 3; m++) {
            float q1 = fmaf(sw.wqs[4 + o * 2 + 0], f1v[m], sw.wqs[4 + o * 2 + 1] * f1v[3 + m]);
            dot = fmaf(q1, k1[o][m], dot);
        }
    }

    g_dot[e] = dot;
    atomicMaxF(&g_m[vv], dot);
}

__global__ void exp_kernel(const int* __restrict__ v, float* __restrict__ out) {
    int e = blockIdx.x * 256 + threadIdx.x;
    if (e >= N_EDGES) return;
    int vv = v[e];
    float p = __expf(g_dot[e] - g_m[vv]);
    out[e] = p;
    atomicAdd(&g_s[vv], p);
}

__global__ void norm_kernel(const int* __restrict__ v, float* __restrict__ out) {
    int t = blockIdx.x * 256 + threadIdx.x;
    if (t >= HALF_E) return;
    int2 vv = ((const int2*)v)[t];
    float2 o = ((const float2*)out)[t];
    o.x = o.x / g_s[vv.x];
    o.y = o.y / g_s[vv.y];
    ((float2*)out)[t] = o;
}

extern "C" void kernel_launch(void* const* d_in, const int* in_sizes, int n_in,
                              void* d_out, int out_size) {
    const float* f0    = (const float*)d_in[0];
    const float* f1    = (const float*)d_in[1];
    const float* dist  = (const float*)d_in[2];
    const int*   u     = (const int*)d_in[3];
    const int*   v     = (const int*)d_in[4];
    const float* wq    = (const float*)d_in[5];
    const float* wj00  = (const float*)d_in[6];
    const float* wj01  = (const float*)d_in[7];
    const float* wj10  = (const float*)d_in[8];
    const float* wj11  = (const float*)d_in[9];
    const float* rW1   = (const float*)d_in[10];
    const float* rb1   = (const float*)d_in[11];
    const float* g1    = (const float*)d_in[12];
    const float* be1   = (const float*)d_in[13];
    const float* rW2   = (const float*)d_in[14];
    const float* rb2   = (const float*)d_in[15];
    const float* g2    = (const float*)d_in[16];
    const float* be2   = (const float*)d_in[17];
    const float* W3_00 = (const float*)d_in[18];
    const float* b3_00 = (const float*)d_in[19];
    const float* W3_01 = (const float*)d_in[20];
    const float* b3_01 = (const float*)d_in[21];
    const float* W3_10 = (const float*)d_in[22];
    const float* b3_10 = (const float*)d_in[23];
    const float* W3_11 = (const float*)d_in[24];
    const float* b3_11 = (const float*)d_in[25];
    float* out = (float*)d_out;

    init_kernel<<<(N_NODES + 255) / 256, 256>>>();
    edge_kernel<<<N_EDGES / 128, 128>>>(
        f0, f1, dist, u, v, wq, wj00, wj01, wj10, wj11,
        rW1, rb1, g1, be1, rW2, rb2, g2, be2,
        W3_00, b3_00, W3_01, b3_01, W3_10, b3_10, W3_11, b3_11);
    exp_kernel<<<(N_EDGES + 255) / 256, 256>>>(v, out);
    norm_kernel<<<HALF_E / 256, 256>>>(v, out);
}